// round 14
// baseline (speedup 1.0000x reference)
#include <cuda_runtime.h>
#include <math.h>

#define TT 512
#define BB 256
#define DD 256
#define HH 256
#define KK 256
#define GG 1024  // 4*H

#define RBLK 128     // persistent recurrence grid: 8 batch-groups x 16 n-blocks
#define RTHR 256

// Scratch state (static device globals: allocation-free per harness rules)
__device__ float g_gx[(size_t)TT * BB * GG];   // precomputed x-path gates + biases
__device__ float g_hm[2][BB * HH];             // double-buffered (h .* mask_h)
__device__ unsigned g_bar = 0;                 // grid barrier counter
__device__ unsigned g_gen = 0;                 // grid barrier generation

// ===========================================================================
// Split-tf32 helpers (sm_80+ mma.sync — valid on sm_100a)
// ===========================================================================
__device__ __forceinline__ unsigned f2tf(float a) {
    unsigned r;
    asm("cvt.rna.tf32.f32 %0, %1;" : "=r"(r) : "f"(a));
    return r;
}
__device__ __forceinline__ void split_tf32(float a, unsigned& h, unsigned& l) {
    h = f2tf(a);
    l = f2tf(a - __uint_as_float(h));
}
__device__ __forceinline__ void mma_tf32(float* c, const unsigned* a,
                                         unsigned b0, unsigned b1) {
    asm("mma.sync.aligned.m16n8k8.row.col.f32.tf32.tf32.f32 "
        "{%0,%1,%2,%3}, {%4,%5,%6,%7}, {%8,%9}, {%0,%1,%2,%3};"
        : "+f"(c[0]), "+f"(c[1]), "+f"(c[2]), "+f"(c[3])
        : "r"(a[0]), "r"(a[1]), "r"(a[2]), "r"(a[3]), "r"(b0), "r"(b1));
}

// ---------------------------------------------------------------------------
// gemm_x: M-tile 256 per CTA (2 m-tiles per warp) so each B-fragment LDS
// feeds 6 MMAs instead of 3. Fragment mappings identical to R12 (proven).
// Dynamic smem: As 256*36 | Bh 64*36 | Bl 64*36 = 13824 floats = 55.3 KB.
// ---------------------------------------------------------------------------
#define GAS 0
#define GBH 9216
#define GBL 11520
#define GSM_FLOATS 13824

__global__ __launch_bounds__(256) void gemm_x_tc(
    const float* __restrict__ X, const float* __restrict__ MX,
    const float* __restrict__ W, const float* __restrict__ bih,
    const float* __restrict__ bhh)
{
    extern __shared__ float gsm[];
    float* As = gsm + GAS;     // [256][36] raw A
    float* Bh = gsm + GBH;     // [64][36]
    float* Bl = gsm + GBL;     // [64][36]

    const int m0 = blockIdx.x * 256;
    const int n0 = blockIdx.y * 64;
    const int tid = threadIdx.x;
    const int warp = tid >> 5;
    const int lane = tid & 31;
    const int g = lane >> 2;
    const int tg = lane & 3;
    const int wm = warp * 16;

    float acc[2][8][4];
#pragma unroll
    for (int mt = 0; mt < 2; mt++)
#pragma unroll
        for (int nt = 0; nt < 8; nt++)
#pragma unroll
            for (int i = 0; i < 4; i++) acc[mt][nt][i] = 0.0f;

    for (int kc = 0; kc < 8; kc++) {
        const int k0 = kc * 32;
        __syncthreads();
        // A chunk: 256 rows x 32 k, float4 STS, masked by MX
#pragma unroll
        for (int q = 0; q < 8; q++) {
            int i = tid + 256 * q;          // 0..2047 float4 slots
            int row = i >> 3;               // 8 float4 per row
            int kq = (i & 7) * 4;
            float4 xv = *(const float4*)(X + (size_t)(m0 + row) * KK + k0 + kq);
            float4 mv = *(const float4*)(MX + (size_t)((m0 + row) & (BB - 1)) * KK + k0 + kq);
            xv.x *= mv.x; xv.y *= mv.y; xv.z *= mv.z; xv.w *= mv.w;
            *(float4*)&As[row * 36 + kq] = xv;
        }
        // B chunk: 64 rows x 32 k — split hi/lo once at load (R12-proven)
#pragma unroll
        for (int q = 0; q < 2; q++) {
            int i = tid + 256 * q;          // 0..511
            int row = i >> 3;
            int kq = (i & 7) * 4;
            float4 wv = *(const float4*)(W + (size_t)(n0 + row) * KK + k0 + kq);
            unsigned h, l;
            split_tf32(wv.x, h, l);
            Bh[row * 36 + kq]     = __uint_as_float(h); Bl[row * 36 + kq]     = __uint_as_float(l);
            split_tf32(wv.y, h, l);
            Bh[row * 36 + kq + 1] = __uint_as_float(h); Bl[row * 36 + kq + 1] = __uint_as_float(l);
            split_tf32(wv.z, h, l);
            Bh[row * 36 + kq + 2] = __uint_as_float(h); Bl[row * 36 + kq + 2] = __uint_as_float(l);
            split_tf32(wv.w, h, l);
            Bh[row * 36 + kq + 3] = __uint_as_float(h); Bl[row * 36 + kq + 3] = __uint_as_float(l);
        }
        __syncthreads();

#pragma unroll
        for (int ks = 0; ks < 4; ks++) {
            const int kk = ks * 8;
            // A fragments for both m-tiles (split once per use — not redundant)
            unsigned ah[2][4], al[2][4];
#pragma unroll
            for (int mt = 0; mt < 2; mt++) {
                const int rb = mt * 128 + wm;
                split_tf32(As[(rb + g) * 36 + kk + tg],         ah[mt][0], al[mt][0]);
                split_tf32(As[(rb + g + 8) * 36 + kk + tg],     ah[mt][1], al[mt][1]);
                split_tf32(As[(rb + g) * 36 + kk + tg + 4],     ah[mt][2], al[mt][2]);
                split_tf32(As[(rb + g + 8) * 36 + kk + tg + 4], ah[mt][3], al[mt][3]);
            }
#pragma unroll
            for (int nt = 0; nt < 8; nt++) {
                unsigned bh0 = __float_as_uint(Bh[(nt * 8 + g) * 36 + kk + tg]);
                unsigned bh1 = __float_as_uint(Bh[(nt * 8 + g) * 36 + kk + tg + 4]);
                unsigned bl0 = __float_as_uint(Bl[(nt * 8 + g) * 36 + kk + tg]);
                unsigned bl1 = __float_as_uint(Bl[(nt * 8 + g) * 36 + kk + tg + 4]);
#pragma unroll
                for (int mt = 0; mt < 2; mt++) {
                    mma_tf32(acc[mt][nt], ah[mt], bh0, bh1);
                    mma_tf32(acc[mt][nt], ah[mt], bl0, bl1);
                    mma_tf32(acc[mt][nt], al[mt], bh0, bh1);
                }
            }
        }
    }

    // epilogue: add biases, store float2 pairs (both m-tiles)
#pragma unroll
    for (int nt = 0; nt < 8; nt++) {
        const int n = n0 + nt * 8 + tg * 2;
        const float bs0 = bih[n] + bhh[n];
        const float bs1 = bih[n + 1] + bhh[n + 1];
#pragma unroll
        for (int mt = 0; mt < 2; mt++) {
            const int m = m0 + mt * 128 + wm + g;
            float2 r0 = make_float2(acc[mt][nt][0] + bs0, acc[mt][nt][1] + bs1);
            float2 r1 = make_float2(acc[mt][nt][2] + bs0, acc[mt][nt][3] + bs1);
            *(float2*)&g_gx[(size_t)m * GG + n] = r0;
            *(float2*)&g_gx[(size_t)(m + 8) * GG + n] = r1;
        }
    }
}

// ---------------------------------------------------------------------------
// Grid-wide barrier, RBLK arrivals. All 128 CTAs co-resident (1 CTA/SM by
// smem; 128 <= 148 SMs).
// ---------------------------------------------------------------------------
__device__ __forceinline__ void grid_barrier()
{
    __threadfence();
    __syncthreads();
    if (threadIdx.x == 0) {
        unsigned gen = *(volatile unsigned*)&g_gen;
        if (atomicAdd(&g_bar, 1u) == (unsigned)(RBLK - 1)) {
            g_bar = 0;
            __threadfence();
            *(volatile unsigned*)&g_gen = gen + 1;
        } else {
            while (*(volatile unsigned*)&g_gen == gen) { }
        }
    }
    __syncthreads();
}

__device__ __forceinline__ float fsig(float x) {
    return __fdividef(1.0f, 1.0f + __expf(-x));
}
__device__ __forceinline__ float ftanh(float x) {
    return __fdividef(2.0f, 1.0f + __expf(-2.0f * x)) - 1.0f;
}

// ---------------------------------------------------------------------------
// Tensor-core persistent recurrence (R13 structure) with A PRE-SPLIT at load:
// the loader splits each hm element once into Ah/Al; the MMA loop is pure
// LDS + MMA (zero cvt — removes the 4x-redundant in-loop splits, alu pipe).
// Dynamic smem floats:
//   Wh 18432 | Wl 18432 | Ah 8320 | Al 8320 | STG 2176 | bsz 512 = 56192
//   = 224768 bytes < 227 KB cap.
// ---------------------------------------------------------------------------
#define SM_WH   0
#define SM_WL   18432
#define SM_AH   36864
#define SM_AL   45184
#define SM_STG  53504
#define SM_BSZ  55680
#define SM_FLOATS 56192

__global__ __launch_bounds__(RTHR) void recurrent_tc(
    const float* __restrict__ mh, const float* __restrict__ Whh,
    const int* __restrict__ bsz, const float* __restrict__ h0,
    const float* __restrict__ c0, float* __restrict__ out)
{
    extern __shared__ float sm[];
    float* Wh = sm + SM_WH;
    float* Wl = sm + SM_WL;
    float* Ah = sm + SM_AH;    // [32][260] hm hi
    float* Al = sm + SM_AL;    // [32][260] hm lo
    float* STG = sm + SM_STG;  // [32][68] gate staging
    int* SB = (int*)(sm + SM_BSZ);

    const int bb = blockIdx.x >> 4;   // batch group 0..7
    const int nb = blockIdx.x & 15;   // n-block 0..15
    const int b0 = bb * 32;
    const int j0 = nb * 16;
    const int tid = threadIdx.x;
    const int warp = tid >> 5;
    const int lane = tid & 31;
    const int g = lane >> 2;
    const int tg = lane & 3;
    const int wm = (warp & 1) * 16;        // warp's M-tile (rows wm..wm+15)
    const int np = (warp >> 1) * 16;       // warp's n-local base (2 tiles of 8)

    // ---- one-time: split W_hh slice into Wh/Wl [kc][nloc][36] ----
    for (int i = tid; i < 64 * 256; i += RTHR) {
        int nloc = i >> 8;
        int k = i & 255;
        int nglob = (nloc >> 4) * 256 + j0 + (nloc & 15);
        unsigned h, l;
        split_tf32(Whh[(size_t)nglob * KK + k], h, l);
        int idx = ((k >> 5) * 64 + nloc) * 36 + (k & 31);
        Wh[idx] = __uint_as_float(h);
        Wl[idx] = __uint_as_float(l);
    }
    for (int i = tid; i < TT; i += RTHR) SB[i] = bsz[i];

    // ---- one-time: register state ----
    const int jl = tid & 15;
    const int bl0 = tid >> 4;              // 0..15
    const int j = j0 + jl;
    float mhv[2], cc[2], hh[2];
#pragma unroll
    for (int r = 0; r < 2; r++) {
        int b = b0 + bl0 + 16 * r;
        mhv[r] = mh[b * HH + j];
        cc[r] = c0[b * HH + j];
        hh[r] = h0[b * HH + j];
        g_hm[0][b * HH + j] = hh[r] * mhv[r];
    }
    __syncthreads();
    grid_barrier();    // hm[0] + all CTAs' W splits ready

    // A loader mapping: 32 rows x 256 k, 8 float4 per thread
    const int arow = tid >> 3;
    const int akq = (tid & 7) * 4;

    // prefetch gx(0)
    float gx[2][4];
#pragma unroll
    for (int r = 0; r < 2; r++) {
        const float* gp = g_gx + (size_t)(b0 + bl0 + 16 * r) * GG + j;
#pragma unroll
        for (int q = 0; q < 4; q++) gx[r][q] = __ldcg(gp + q * 256);
    }

    for (int t = 0; t < TT; t++) {
        const float* __restrict__ hmp = g_hm[t & 1];
        float* __restrict__ hmn = g_hm[(t & 1) ^ 1];

        // load hm tile and pre-split (one split per element per step)
        {
            const float* src = hmp + (size_t)(b0 + arow) * HH + akq;
#pragma unroll
            for (int q = 0; q < 8; q++) {
                float4 v = __ldcg((const float4*)(src + q * 32));
                const int kb = arow * 260 + akq + q * 32;
                unsigned h, l;
                split_tf32(v.x, h, l); Ah[kb]     = __uint_as_float(h); Al[kb]     = __uint_as_float(l);
                split_tf32(v.y, h, l); Ah[kb + 1] = __uint_as_float(h); Al[kb + 1] = __uint_as_float(l);
                split_tf32(v.z, h, l); Ah[kb + 2] = __uint_as_float(h); Al[kb + 2] = __uint_as_float(l);
                split_tf32(v.w, h, l); Ah[kb + 3] = __uint_as_float(h); Al[kb + 3] = __uint_as_float(l);
            }
        }
        __syncthreads();

        // MMA: 2 output tiles per warp, K=256 in 32 k8-steps, pure LDS+MMA
        float acc0[4] = {0.f, 0.f, 0.f, 0.f};
        float acc1[4] = {0.f, 0.f, 0.f, 0.f};
        for (int kc = 0; kc < 8; kc++) {
#pragma unroll
            for (int ks = 0; ks < 4; ks++) {
                const int kk = ks * 8;
                const int kg = kc * 32 + kk;
                unsigned ah[4], al[4];
                ah[0] = __float_as_uint(Ah[(wm + g) * 260 + kg + tg]);
                ah[1] = __float_as_uint(Ah[(wm + g + 8) * 260 + kg + tg]);
                ah[2] = __float_as_uint(Ah[(wm + g) * 260 + kg + tg + 4]);
                ah[3] = __float_as_uint(Ah[(wm + g + 8) * 260 + kg + tg + 4]);
                al[0] = __float_as_uint(Al[(wm + g) * 260 + kg + tg]);
                al[1] = __float_as_uint(Al[(wm + g + 8) * 260 + kg + tg]);
                al[2] = __float_as_uint(Al[(wm + g) * 260 + kg + tg + 4]);
                al[3] = __float_as_uint(Al[(wm + g + 8) * 260 + kg + tg + 4]);
                {
                    const int wbase = ((kc * 64) + np + g) * 36 + kk + tg;
                    unsigned bh0 = __float_as_uint(Wh[wbase]);
                    unsigned bh1 = __float_as_uint(Wh[wbase + 4]);
                    unsigned bl0_ = __float_as_uint(Wl[wbase]);
                    unsigned bl1_ = __float_as_uint(Wl[wbase + 4]);
                    mma_tf32(acc0, ah, bh0, bh1);
                    mma_tf32(acc0, ah, bl0_, bl1_);
                    mma_tf32(acc0, al, bh0, bh1);
                }
                {
                    const int wbase = ((kc * 64) + np + 8 + g) * 36 + kk + tg;
                    unsigned bh0 = __float_as_uint(Wh[wbase]);
                    unsigned bh1 = __float_as_uint(Wh[wbase + 4]);
                    unsigned bl0_ = __float_as_uint(Wl[wbase]);
                    unsigned bl1_ = __float_as_uint(Wl[wbase + 4]);
                    mma_tf32(acc1, ah, bh0, bh1);
                    mma_tf32(acc1, ah, bl0_, bl1_);
                    mma_tf32(acc1, al, bh0, bh1);
                }
            }
        }

        // stage accumulators: STG[row][nloc]
        {
            int nc0 = np + tg * 2;
            *(float2*)&STG[(wm + g) * 68 + nc0]     = make_float2(acc0[0], acc0[1]);
            *(float2*)&STG[(wm + g + 8) * 68 + nc0] = make_float2(acc0[2], acc0[3]);
            int nc1 = np + 8 + tg * 2;
            *(float2*)&STG[(wm + g) * 68 + nc1]     = make_float2(acc1[0], acc1[1]);
            *(float2*)&STG[(wm + g + 8) * 68 + nc1] = make_float2(acc1[2], acc1[3]);
        }
        __syncthreads();

        // pointwise: 2 owned cells
        const int size = SB[t];
        float o[2];
#pragma unroll
        for (int r = 0; r < 2; r++) {
            const int bl = bl0 + 16 * r;
            const int b = b0 + bl;
            float a0 = STG[bl * 68 + jl]      + gx[r][0];
            float a1 = STG[bl * 68 + 16 + jl] + gx[r][1];
            float a2 = STG[bl * 68 + 32 + jl] + gx[r][2];
            float a3 = STG[bl * 68 + 48 + jl] + gx[r][3];
            float iv = fsig(a0), fv = fsig(a1), gv = ftanh(a2), ov = fsig(a3);
            float cn = fv * cc[r] + iv * gv;
            float hn = ov * ftanh(cn);
            bool act = b < size;
            if (act) { cc[r] = cn; hh[r] = hn; }
            o[r] = act ? hn : 0.0f;
            hmn[b * HH + j] = hh[r] * mhv[r];
        }

        // prefetch gx(t+1)
        if (t + 1 < TT) {
#pragma unroll
            for (int r = 0; r < 2; r++) {
                const float* gp = g_gx + ((size_t)(t + 1) * BB + b0 + bl0 + 16 * r) * GG + j;
#pragma unroll
                for (int q = 0; q < 4; q++) gx[r][q] = __ldcg(gp + q * 256);
            }
        }

        grid_barrier();

#pragma unroll
        for (int r = 0; r < 2; r++)
            out[((size_t)t * BB + b0 + bl0 + 16 * r) * HH + j] = o[r];
    }

    // final hn, cn
    const size_t TBH = (size_t)TT * BB * HH;
#pragma unroll
    for (int r = 0; r < 2; r++) {
        int b = b0 + bl0 + 16 * r;
        out[TBH + b * HH + j] = hh[r];
        out[TBH + BB * HH + b * HH + j] = cc[r];
    }
}

// ---------------------------------------------------------------------------
extern "C" void kernel_launch(void* const* d_in, const int* in_sizes, int n_in,
                              void* d_out, int out_size)
{
    const float* X   = (const float*)d_in[0];   // [T,B,D]
    const float* h0  = (const float*)d_in[1];   // [B,H]
    const float* c0  = (const float*)d_in[2];   // [B,H]
    const float* mx  = (const float*)d_in[3];   // [B,D]
    const float* mh  = (const float*)d_in[4];   // [B,H]
    const float* Wih = (const float*)d_in[5];   // [4H,D]
    const float* Whh = (const float*)d_in[6];   // [4H,H]
    const float* bih = (const float*)d_in[7];   // [4H]
    const float* bhh = (const float*)d_in[8];   // [4H]
    const int*   bsz = (const int*)d_in[9];     // [T]
    float* out = (float*)d_out;                 // [T*B*H] ++ [B*H] ++ [B*H]

    static int smem_set = 0;
    if (!smem_set) {
        cudaFuncSetAttribute(recurrent_tc,
                             cudaFuncAttributeMaxDynamicSharedMemorySize,
                             SM_FLOATS * 4);
        cudaFuncSetAttribute(gemm_x_tc,
                             cudaFuncAttributeMaxDynamicSharedMemorySize,
                             GSM_FLOATS * 4);
        smem_set = 1;
    }

    gemm_x_tc<<<dim3((TT * BB) / 256, GG / 64), 256, GSM_FLOATS * 4>>>(X, mx, Wih, bih, bhh);
    recurrent_tc<<<RBLK, RTHR, SM_FLOATS * 4>>>(mh, Whh, bsz, h0, c0, out);
}

// round 15
// speedup vs baseline: 1.0314x; 1.0314x over previous
#include <cuda_runtime.h>
#include <math.h>

#define TT 512
#define BB 256
#define DD 256
#define HH 256
#define KK 256
#define GG 1024  // 4*H

#define RBLK 128     // persistent recurrence grid: 8 batch-groups x 16 n-blocks
#define RTHR 256

// Scratch state (static device globals: allocation-free per harness rules)
__device__ float g_gx[(size_t)TT * BB * GG];   // precomputed x-path gates + biases
__device__ float g_hm[2][BB * HH];             // double-buffered (h .* mask_h)
__device__ unsigned g_bar = 0;                 // grid barrier counter
__device__ unsigned g_gen = 0;                 // grid barrier generation

// ===========================================================================
// Split-tf32 helpers (sm_80+ mma.sync — valid on sm_100a)
// ===========================================================================
__device__ __forceinline__ unsigned f2tf(float a) {
    unsigned r;
    asm("cvt.rna.tf32.f32 %0, %1;" : "=r"(r) : "f"(a));
    return r;
}
__device__ __forceinline__ void split_tf32(float a, unsigned& h, unsigned& l) {
    h = f2tf(a);
    l = f2tf(a - __uint_as_float(h));
}
__device__ __forceinline__ void mma_tf32(float* c, const unsigned* a,
                                         unsigned b0, unsigned b1) {
    asm("mma.sync.aligned.m16n8k8.row.col.f32.tf32.tf32.f32 "
        "{%0,%1,%2,%3}, {%4,%5,%6,%7}, {%8,%9}, {%0,%1,%2,%3};"
        : "+f"(c[0]), "+f"(c[1]), "+f"(c[2]), "+f"(c[3])
        : "r"(a[0]), "r"(a[1]), "r"(a[2]), "r"(a[3]), "r"(b0), "r"(b1));
}

// Dummy no-op kernels: shift ncu's -s 5 -c 1 capture window onto gemm_x_tc
// (launch sequence per call: dummy, gemm, recurrence, dummy -> launch #6 = gemm).
__global__ void dummy_k() {}

// ---------------------------------------------------------------------------
// gemm_x — R12 tile shape (proven), inner loop reordered TERM-MAJOR:
// B fragments preloaded to registers, then all hh MMAs, all hl, all lh —
// consecutive MMAs hit different accumulators (no dependency stalls).
// ---------------------------------------------------------------------------
__global__ __launch_bounds__(256) void gemm_x_tc(
    const float* __restrict__ X, const float* __restrict__ MX,
    const float* __restrict__ W, const float* __restrict__ bih,
    const float* __restrict__ bhh)
{
    __shared__ float As[128][36];
    __shared__ float Bh[64][36], Bl[64][36];

    const int m0 = blockIdx.x * 128;
    const int n0 = blockIdx.y * 64;
    const int tid = threadIdx.x;
    const int warp = tid >> 5;
    const int lane = tid & 31;
    const int g = lane >> 2;
    const int tg = lane & 3;
    const int wm = warp * 16;

    float acc[8][4];
#pragma unroll
    for (int nt = 0; nt < 8; nt++)
#pragma unroll
        for (int i = 0; i < 4; i++) acc[nt][i] = 0.0f;

    for (int kc = 0; kc < 8; kc++) {
        const int k0 = kc * 32;
        __syncthreads();
#pragma unroll
        for (int q = 0; q < 4; q++) {
            int i = tid + 256 * q;
            int row = i >> 3;
            int kq = (i & 7) * 4;
            float4 xv = *(const float4*)(X + (size_t)(m0 + row) * KK + k0 + kq);
            float4 mv = *(const float4*)(MX + (size_t)((m0 + row) & (BB - 1)) * KK + k0 + kq);
            xv.x *= mv.x; xv.y *= mv.y; xv.z *= mv.z; xv.w *= mv.w;
            *(float4*)&As[row][kq] = xv;
        }
#pragma unroll
        for (int q = 0; q < 2; q++) {
            int i = tid + 256 * q;
            int row = i >> 3;
            int kq = (i & 7) * 4;
            float4 wv = *(const float4*)(W + (size_t)(n0 + row) * KK + k0 + kq);
            unsigned h, l;
            split_tf32(wv.x, h, l);
            Bh[row][kq]     = __uint_as_float(h); Bl[row][kq]     = __uint_as_float(l);
            split_tf32(wv.y, h, l);
            Bh[row][kq + 1] = __uint_as_float(h); Bl[row][kq + 1] = __uint_as_float(l);
            split_tf32(wv.z, h, l);
            Bh[row][kq + 2] = __uint_as_float(h); Bl[row][kq + 2] = __uint_as_float(l);
            split_tf32(wv.w, h, l);
            Bh[row][kq + 3] = __uint_as_float(h); Bl[row][kq + 3] = __uint_as_float(l);
        }
        __syncthreads();

#pragma unroll
        for (int ks = 0; ks < 4; ks++) {
            const int kk = ks * 8;
            unsigned ah[4], al[4];
            split_tf32(As[wm + g][kk + tg],         ah[0], al[0]);
            split_tf32(As[wm + g + 8][kk + tg],     ah[1], al[1]);
            split_tf32(As[wm + g][kk + tg + 4],     ah[2], al[2]);
            split_tf32(As[wm + g + 8][kk + tg + 4], ah[3], al[3]);
            // preload all B fragments
            unsigned bh0[8], bh1[8], bl0[8], bl1[8];
#pragma unroll
            for (int nt = 0; nt < 8; nt++) {
                bh0[nt] = __float_as_uint(Bh[nt * 8 + g][kk + tg]);
                bh1[nt] = __float_as_uint(Bh[nt * 8 + g][kk + tg + 4]);
                bl0[nt] = __float_as_uint(Bl[nt * 8 + g][kk + tg]);
                bl1[nt] = __float_as_uint(Bl[nt * 8 + g][kk + tg + 4]);
            }
            // term-major: consecutive MMAs are independent
#pragma unroll
            for (int nt = 0; nt < 8; nt++) mma_tf32(acc[nt], ah, bh0[nt], bh1[nt]);
#pragma unroll
            for (int nt = 0; nt < 8; nt++) mma_tf32(acc[nt], ah, bl0[nt], bl1[nt]);
#pragma unroll
            for (int nt = 0; nt < 8; nt++) mma_tf32(acc[nt], al, bh0[nt], bh1[nt]);
        }
    }

#pragma unroll
    for (int nt = 0; nt < 8; nt++) {
        const int n = n0 + nt * 8 + tg * 2;
        const float bs0 = bih[n] + bhh[n];
        const float bs1 = bih[n + 1] + bhh[n + 1];
        const int m = m0 + wm + g;
        float2 r0 = make_float2(acc[nt][0] + bs0, acc[nt][1] + bs1);
        float2 r1 = make_float2(acc[nt][2] + bs0, acc[nt][3] + bs1);
        *(float2*)&g_gx[(size_t)m * GG + n] = r0;
        *(float2*)&g_gx[(size_t)(m + 8) * GG + n] = r1;
    }
}

// ---------------------------------------------------------------------------
// Grid-wide barrier, RBLK arrivals (128 CTAs co-resident: 1 CTA/SM by smem).
// ---------------------------------------------------------------------------
__device__ __forceinline__ void grid_barrier()
{
    __threadfence();
    __syncthreads();
    if (threadIdx.x == 0) {
        unsigned gen = *(volatile unsigned*)&g_gen;
        if (atomicAdd(&g_bar, 1u) == (unsigned)(RBLK - 1)) {
            g_bar = 0;
            __threadfence();
            *(volatile unsigned*)&g_gen = gen + 1;
        } else {
            while (*(volatile unsigned*)&g_gen == gen) { }
        }
    }
    __syncthreads();
}

__device__ __forceinline__ float fsig(float x) {
    return __fdividef(1.0f, 1.0f + __expf(-x));
}
__device__ __forceinline__ float ftanh(float x) {
    return __fdividef(2.0f, 1.0f + __expf(-2.0f * x)) - 1.0f;
}

// ---------------------------------------------------------------------------
// Tensor-core persistent recurrence (R14: pre-split A) + 6 independent
// accumulator chains (hh/hl/lh per output tile), term-major issue — no
// accumulator dependency stalls in the MMA loop.
// ---------------------------------------------------------------------------
#define SM_WH   0
#define SM_WL   18432
#define SM_AH   36864
#define SM_AL   45184
#define SM_STG  53504
#define SM_BSZ  55680
#define SM_FLOATS 56192

__global__ __launch_bounds__(RTHR) void recurrent_tc(
    const float* __restrict__ mh, const float* __restrict__ Whh,
    const int* __restrict__ bsz, const float* __restrict__ h0,
    const float* __restrict__ c0, float* __restrict__ out)
{
    extern __shared__ float sm[];
    float* Wh = sm + SM_WH;
    float* Wl = sm + SM_WL;
    float* Ah = sm + SM_AH;    // [32][260] hm hi
    float* Al = sm + SM_AL;    // [32][260] hm lo
    float* STG = sm + SM_STG;  // [32][68] gate staging
    int* SB = (int*)(sm + SM_BSZ);

    const int bb = blockIdx.x >> 4;
    const int nb = blockIdx.x & 15;
    const int b0 = bb * 32;
    const int j0 = nb * 16;
    const int tid = threadIdx.x;
    const int warp = tid >> 5;
    const int lane = tid & 31;
    const int g = lane >> 2;
    const int tg = lane & 3;
    const int wm = (warp & 1) * 16;
    const int np = (warp >> 1) * 16;

    // one-time: split W_hh slice into Wh/Wl [kc][nloc][36]
    for (int i = tid; i < 64 * 256; i += RTHR) {
        int nloc = i >> 8;
        int k = i & 255;
        int nglob = (nloc >> 4) * 256 + j0 + (nloc & 15);
        unsigned h, l;
        split_tf32(Whh[(size_t)nglob * KK + k], h, l);
        int idx = ((k >> 5) * 64 + nloc) * 36 + (k & 31);
        Wh[idx] = __uint_as_float(h);
        Wl[idx] = __uint_as_float(l);
    }
    for (int i = tid; i < TT; i += RTHR) SB[i] = bsz[i];

    // one-time: register state
    const int jl = tid & 15;
    const int bl0 = tid >> 4;
    const int j = j0 + jl;
    float mhv[2], cc[2], hh[2];
#pragma unroll
    for (int r = 0; r < 2; r++) {
        int b = b0 + bl0 + 16 * r;
        mhv[r] = mh[b * HH + j];
        cc[r] = c0[b * HH + j];
        hh[r] = h0[b * HH + j];
        g_hm[0][b * HH + j] = hh[r] * mhv[r];
    }
    __syncthreads();
    grid_barrier();

    const int arow = tid >> 3;
    const int akq = (tid & 7) * 4;

    float gx[2][4];
#pragma unroll
    for (int r = 0; r < 2; r++) {
        const float* gp = g_gx + (size_t)(b0 + bl0 + 16 * r) * GG + j;
#pragma unroll
        for (int q = 0; q < 4; q++) gx[r][q] = __ldcg(gp + q * 256);
    }

    for (int t = 0; t < TT; t++) {
        const float* __restrict__ hmp = g_hm[t & 1];
        float* __restrict__ hmn = g_hm[(t & 1) ^ 1];

        // load hm tile and pre-split (one split per element per step)
        {
            const float* src = hmp + (size_t)(b0 + arow) * HH + akq;
#pragma unroll
            for (int q = 0; q < 8; q++) {
                float4 v = __ldcg((const float4*)(src + q * 32));
                const int kb = arow * 260 + akq + q * 32;
                unsigned h, l;
                split_tf32(v.x, h, l); Ah[kb]     = __uint_as_float(h); Al[kb]     = __uint_as_float(l);
                split_tf32(v.y, h, l); Ah[kb + 1] = __uint_as_float(h); Al[kb + 1] = __uint_as_float(l);
                split_tf32(v.z, h, l); Ah[kb + 2] = __uint_as_float(h); Al[kb + 2] = __uint_as_float(l);
                split_tf32(v.w, h, l); Ah[kb + 3] = __uint_as_float(h); Al[kb + 3] = __uint_as_float(l);
            }
        }
        __syncthreads();

        // MMA: 2 output tiles x 3 term-chains = 6 independent accumulators
        float a0h[4] = {0,0,0,0}, a0m[4] = {0,0,0,0}, a0l[4] = {0,0,0,0};
        float a1h[4] = {0,0,0,0}, a1m[4] = {0,0,0,0}, a1l[4] = {0,0,0,0};
        for (int kc = 0; kc < 8; kc++) {
#pragma unroll
            for (int ks = 0; ks < 4; ks++) {
                const int kk = ks * 8;
                const int kg = kc * 32 + kk;
                unsigned ah[4], al[4];
                ah[0] = __float_as_uint(Ah[(wm + g) * 260 + kg + tg]);
                ah[1] = __float_as_uint(Ah[(wm + g + 8) * 260 + kg + tg]);
                ah[2] = __float_as_uint(Ah[(wm + g) * 260 + kg + tg + 4]);
                ah[3] = __float_as_uint(Ah[(wm + g + 8) * 260 + kg + tg + 4]);
                al[0] = __float_as_uint(Al[(wm + g) * 260 + kg + tg]);
                al[1] = __float_as_uint(Al[(wm + g + 8) * 260 + kg + tg]);
                al[2] = __float_as_uint(Al[(wm + g) * 260 + kg + tg + 4]);
                al[3] = __float_as_uint(Al[(wm + g + 8) * 260 + kg + tg + 4]);
                const int w0 = ((kc * 64) + np + g) * 36 + kk + tg;
                const int w1 = ((kc * 64) + np + 8 + g) * 36 + kk + tg;
                unsigned b0h0 = __float_as_uint(Wh[w0]);
                unsigned b0h1 = __float_as_uint(Wh[w0 + 4]);
                unsigned b0l0 = __float_as_uint(Wl[w0]);
                unsigned b0l1 = __float_as_uint(Wl[w0 + 4]);
                unsigned b1h0 = __float_as_uint(Wh[w1]);
                unsigned b1h1 = __float_as_uint(Wh[w1 + 4]);
                unsigned b1l0 = __float_as_uint(Wl[w1]);
                unsigned b1l1 = __float_as_uint(Wl[w1 + 4]);
                // term-major, all independent
                mma_tf32(a0h, ah, b0h0, b0h1);
                mma_tf32(a1h, ah, b1h0, b1h1);
                mma_tf32(a0m, ah, b0l0, b0l1);
                mma_tf32(a1m, ah, b1l0, b1l1);
                mma_tf32(a0l, al, b0h0, b0h1);
                mma_tf32(a1l, al, b1h0, b1h1);
            }
        }
        float acc0[4], acc1[4];
#pragma unroll
        for (int i = 0; i < 4; i++) {
            acc0[i] = a0h[i] + a0m[i] + a0l[i];
            acc1[i] = a1h[i] + a1m[i] + a1l[i];
        }

        // stage accumulators: STG[row][nloc]
        {
            int nc0 = np + tg * 2;
            *(float2*)&STG[(wm + g) * 68 + nc0]     = make_float2(acc0[0], acc0[1]);
            *(float2*)&STG[(wm + g + 8) * 68 + nc0] = make_float2(acc0[2], acc0[3]);
            int nc1 = np + 8 + tg * 2;
            *(float2*)&STG[(wm + g) * 68 + nc1]     = make_float2(acc1[0], acc1[1]);
            *(float2*)&STG[(wm + g + 8) * 68 + nc1] = make_float2(acc1[2], acc1[3]);
        }
        __syncthreads();

        // pointwise: 2 owned cells
        const int size = SB[t];
        float o[2];
#pragma unroll
        for (int r = 0; r < 2; r++) {
            const int bl = bl0 + 16 * r;
            const int b = b0 + bl;
            float a0 = STG[bl * 68 + jl]      + gx[r][0];
            float a1 = STG[bl * 68 + 16 + jl] + gx[r][1];
            float a2 = STG[bl * 68 + 32 + jl] + gx[r][2];
            float a3 = STG[bl * 68 + 48 + jl] + gx[r][3];
            float iv = fsig(a0), fv = fsig(a1), gv = ftanh(a2), ov = fsig(a3);
            float cn = fv * cc[r] + iv * gv;
            float hn = ov * ftanh(cn);
            bool act = b < size;
            if (act) { cc[r] = cn; hh[r] = hn; }
            o[r] = act ? hn : 0.0f;
            hmn[b * HH + j] = hh[r] * mhv[r];
        }

        // prefetch gx(t+1)
        if (t + 1 < TT) {
#pragma unroll
            for (int r = 0; r < 2; r++) {
                const float* gp = g_gx + ((size_t)(t + 1) * BB + b0 + bl0 + 16 * r) * GG + j;
#pragma unroll
                for (int q = 0; q < 4; q++) gx[r][q] = __ldcg(gp + q * 256);
            }
        }

        grid_barrier();

#pragma unroll
        for (int r = 0; r < 2; r++)
            out[((size_t)t * BB + b0 + bl0 + 16 * r) * HH + j] = o[r];
    }

    // final hn, cn
    const size_t TBH = (size_t)TT * BB * HH;
#pragma unroll
    for (int r = 0; r < 2; r++) {
        int b = b0 + bl0 + 16 * r;
        out[TBH + b * HH + j] = hh[r];
        out[TBH + BB * HH + b * HH + j] = cc[r];
    }
}

// ---------------------------------------------------------------------------
extern "C" void kernel_launch(void* const* d_in, const int* in_sizes, int n_in,
                              void* d_out, int out_size)
{
    const float* X   = (const float*)d_in[0];   // [T,B,D]
    const float* h0  = (const float*)d_in[1];   // [B,H]
    const float* c0  = (const float*)d_in[2];   // [B,H]
    const float* mx  = (const float*)d_in[3];   // [B,D]
    const float* mh  = (const float*)d_in[4];   // [B,H]
    const float* Wih = (const float*)d_in[5];   // [4H,D]
    const float* Whh = (const float*)d_in[6];   // [4H,H]
    const float* bih = (const float*)d_in[7];   // [4H]
    const float* bhh = (const float*)d_in[8];   // [4H]
    const int*   bsz = (const int*)d_in[9];     // [T]
    float* out = (float*)d_out;                 // [T*B*H] ++ [B*H] ++ [B*H]

    static int smem_set = 0;
    if (!smem_set) {
        cudaFuncSetAttribute(recurrent_tc,
                             cudaFuncAttributeMaxDynamicSharedMemorySize,
                             SM_FLOATS * 4);
        smem_set = 1;
    }

    // launch pattern (period 4): dummy, gemm, recurrence, dummy
    // -> global launch #6 = gemm_x_tc, so ncu (-s 5 -c 1) captures the GEMM.
    dummy_k<<<1, 32>>>();
    gemm_x_tc<<<dim3((TT * BB) / 128, GG / 64), 256>>>(X, mx, Wih, bih, bhh);
    recurrent_tc<<<RBLK, RTHR, SM_FLOATS * 4>>>(mh, Whh, bsz, h0, c0, out);
    dummy_k<<<1, 32>>>();
}